// round 2
// baseline (speedup 1.0000x reference)
#include <cuda_runtime.h>
#include <math.h>

#define NN 8192
#define FD 128
#define HEPS 1e-7f
#define MAXT (1.0f - 1e-6f)

// Scratch (no allocations allowed)
__device__ float g_U[NN * FD];       // log0(x)
__device__ float g_V[NN * FD];       // log0(h_add(exp0(U@embed), embed_bias))
__device__ float g_AV[NN * FD];      // adj @ g_V
__device__ float g_W[NN * 2 * FD];   // log0(concat(x, exp0(g_AV)))

__device__ __forceinline__ float wsum(float v) {
#pragma unroll
    for (int o = 16; o > 0; o >>= 1) v += __shfl_xor_sync(0xffffffffu, v, o);
    return v;
}

// ---------------------------------------------------------------------------
// Row-wise log map: U = log0(x). One warp per row (128 cols = 32 lanes x float4)
// ---------------------------------------------------------------------------
__global__ void k_logmap(const float* __restrict__ x, float* __restrict__ U) {
    int row = (blockIdx.x * blockDim.x + threadIdx.x) >> 5;
    int lane = threadIdx.x & 31;
    if (row >= NN) return;
    float4 v = ((const float4*)(x + (size_t)row * FD))[lane];
    float ss = wsum(v.x * v.x + v.y * v.y + v.z * v.z + v.w * v.w);
    float n = fmaxf(sqrtf(ss), HEPS);
    float s = atanhf(fminf(n, MAXT)) / n;
    ((float4*)(U + (size_t)row * FD))[lane] =
        make_float4(v.x * s, v.y * s, v.z * s, v.w * s);
}

// ---------------------------------------------------------------------------
// Tiled GEMM  out_pre = A[NN,KD] @ B[KD,128]  with fused Mobius epilogue.
// Block: 128 threads, 32 rows x 128 cols. Warp w owns rows w*8..w*8+7 fully,
// each lane holds 4 consecutive cols -> all row reductions are warp shuffles.
// MODE 0: out = log0(h_add(exp0(T), bias))   (after embed GEMM)
// MODE 1: out = h_add(exp0(T), bias)         (final layer GEMM)
// ---------------------------------------------------------------------------
template <int KD, int MODE>
__global__ void k_gemm_fused(const float* __restrict__ A, const float* __restrict__ B,
                             const float* __restrict__ bias, float* __restrict__ out) {
    __shared__ float As[32][33];     // padded: conflict-free writes, broadcast reads
    __shared__ float Bs[32][FD];
    const int tid = threadIdx.x;     // 128
    const int lane = tid & 31;
    const int wid = tid >> 5;        // 0..3
    const int br = blockIdx.x * 32;

    float acc[8][4];
#pragma unroll
    for (int r = 0; r < 8; r++)
#pragma unroll
        for (int c = 0; c < 4; c++) acc[r][c] = 0.f;

    for (int k0 = 0; k0 < KD; k0 += 32) {
#pragma unroll
        for (int i = 0; i < 8; i++) {               // 32x32 A tile
            int idx = tid + i * 128;
            int r = idx >> 5, k = idx & 31;
            As[r][k] = A[(size_t)(br + r) * KD + k0 + k];
        }
#pragma unroll
        for (int i = 0; i < 32; i++) {              // 32x128 B tile
            int idx = tid + i * 128;
            int k = idx >> 7, c = idx & 127;
            Bs[k][c] = B[(size_t)(k0 + k) * FD + c];
        }
        __syncthreads();
#pragma unroll
        for (int k = 0; k < 32; k++) {
            float4 b = *((const float4*)&Bs[k][lane * 4]);
#pragma unroll
            for (int r = 0; r < 8; r++) {
                float a = As[wid * 8 + r][k];       // warp-broadcast
                acc[r][0] += a * b.x;
                acc[r][1] += a * b.y;
                acc[r][2] += a * b.z;
                acc[r][3] += a * b.w;
            }
        }
        __syncthreads();
    }

    // In-register Mobius epilogue (warp owns full rows)
    float4 bv = ((const float4*)bias)[lane];
    float y2 = wsum(bv.x * bv.x + bv.y * bv.y + bv.z * bv.z + bv.w * bv.w);
#pragma unroll
    for (int r = 0; r < 8; r++) {
        int row = br + wid * 8 + r;
        float t0 = acc[r][0], t1 = acc[r][1], t2 = acc[r][2], t3 = acc[r][3];
        float ss  = wsum(t0 * t0 + t1 * t1 + t2 * t2 + t3 * t3);
        float dtb = wsum(t0 * bv.x + t1 * bv.y + t2 * bv.z + t3 * bv.w);
        // exp0
        float n = fmaxf(sqrtf(ss), HEPS);
        float s = tanhf(n) / n;
        float h0 = t0 * s, h1 = t1 * s, h2 = t2 * s, h3 = t3 * s;
        // h_add(h, bias)
        float x2 = s * s * ss;
        float xy = s * dtb;
        float cnum = 1.f + 2.f * xy + y2;
        float cx = 1.f - x2;
        float inv = 1.f / fmaxf(1.f + 2.f * xy + x2 * y2, HEPS);
        float o0 = (cnum * h0 + cx * bv.x) * inv;
        float o1 = (cnum * h1 + cx * bv.y) * inv;
        float o2 = (cnum * h2 + cx * bv.z) * inv;
        float o3 = (cnum * h3 + cx * bv.w) * inv;
        if (MODE == 0) {  // log0
            float sso = wsum(o0 * o0 + o1 * o1 + o2 * o2 + o3 * o3);
            float no = fmaxf(sqrtf(sso), HEPS);
            float so = atanhf(fminf(no, MAXT)) / no;
            o0 *= so; o1 *= so; o2 *= so; o3 *= so;
        }
        ((float4*)(out + (size_t)row * FD))[lane] = make_float4(o0, o1, o2, o3);
    }
}

// ---------------------------------------------------------------------------
// Sparse-aware SpMM by dense scan: AV = adj @ V.  One warp per output row.
// Streams the 32KB adj row coalesced (x4 unroll for MLP), ballots nonzeros,
// accumulates float4 of V[j] per nonzero (V is L2-resident, 4MB).
// ---------------------------------------------------------------------------
__global__ void k_spmm(const float* __restrict__ adj, const float* __restrict__ V,
                       float* __restrict__ AV) {
    int row = (blockIdx.x * blockDim.x + threadIdx.x) >> 5;
    int lane = threadIdx.x & 31;
    if (row >= NN) return;
    const float* arow = adj + (size_t)row * NN;
    float ax = 0.f, ay = 0.f, az = 0.f, aw = 0.f;
    for (int base = 0; base < NN; base += 128) {
        float a4[4];
#pragma unroll
        for (int q = 0; q < 4; q++) a4[q] = arow[base + q * 32 + lane];
#pragma unroll
        for (int q = 0; q < 4; q++) {
            unsigned m = __ballot_sync(0xffffffffu, a4[q] != 0.f);
            while (m) {
                int src = __ffs(m) - 1;
                m &= m - 1;
                float aj = __shfl_sync(0xffffffffu, a4[q], src);
                float4 v = ((const float4*)(V + (size_t)(base + q * 32 + src) * FD))[lane];
                ax += aj * v.x; ay += aj * v.y; az += aj * v.z; aw += aj * v.w;
            }
        }
    }
    ((float4*)(AV + (size_t)row * FD))[lane] = make_float4(ax, ay, az, aw);
}

// ---------------------------------------------------------------------------
// W = log0(concat(x, exp0(AV))). One warp per row; 256-d norm over both halves.
// ---------------------------------------------------------------------------
__global__ void k_concat_log(const float* __restrict__ x, const float* __restrict__ AV,
                             float* __restrict__ W) {
    int row = (blockIdx.x * blockDim.x + threadIdx.x) >> 5;
    int lane = threadIdx.x & 31;
    if (row >= NN) return;
    float4 av = ((const float4*)(AV + (size_t)row * FD))[lane];
    float ssa = wsum(av.x * av.x + av.y * av.y + av.z * av.z + av.w * av.w);
    float na = fmaxf(sqrtf(ssa), HEPS);
    float sa = tanhf(na) / na;                 // neigh = sa * av
    float4 xv = ((const float4*)(x + (size_t)row * FD))[lane];
    float ssx = wsum(xv.x * xv.x + xv.y * xv.y + xv.z * xv.z + xv.w * xv.w);
    float tot = ssx + sa * sa * ssa;           // ||concat||^2
    float n = fmaxf(sqrtf(tot), HEPS);
    float s = atanhf(fminf(n, MAXT)) / n;
    float* wr = W + (size_t)row * 2 * FD;
    ((float4*)wr)[lane] = make_float4(s * xv.x, s * xv.y, s * xv.z, s * xv.w);
    float sb = s * sa;
    ((float4*)(wr + FD))[lane] = make_float4(sb * av.x, sb * av.y, sb * av.z, sb * av.w);
}

// ---------------------------------------------------------------------------
extern "C" void kernel_launch(void* const* d_in, const int* in_sizes, int n_in,
                              void* d_out, int out_size) {
    const float* x     = (const float*)d_in[0];
    const float* adj   = (const float*)d_in[1];
    const float* embed = (const float*)d_in[2];
    const float* layer = (const float*)d_in[3];
    const float* eb    = (const float*)d_in[4];
    const float* lb    = (const float*)d_in[5];
    float* out = (float*)d_out;
    (void)in_sizes; (void)n_in; (void)out_size;

    float *pU, *pV, *pAV, *pW;
    cudaGetSymbolAddress((void**)&pU, g_U);
    cudaGetSymbolAddress((void**)&pV, g_V);
    cudaGetSymbolAddress((void**)&pAV, g_AV);
    cudaGetSymbolAddress((void**)&pW, g_W);

    // 1. U = log0(x)
    k_logmap<<<NN / 8, 256>>>(x, pU);
    // 2. V = log0(h_add(exp0(U @ embed), embed_bias))
    k_gemm_fused<FD, 0><<<NN / 32, 128>>>(pU, embed, eb, pV);
    // 3. AV = adj @ V
    k_spmm<<<NN / 8, 256>>>(adj, pV, pAV);
    // 4. W = log0(concat(x, exp0(AV)))
    k_concat_log<<<NN / 8, 256>>>(x, pAV, pW);
    // 5. out = h_add(exp0(W @ layer), layer_bias)
    k_gemm_fused<2 * FD, 1><<<NN / 32, 128>>>(pW, layer, lb, out);
}